// round 2
// baseline (speedup 1.0000x reference)
#include <cuda_runtime.h>

#define NB   32
#define HWD  128
#define CONDD 256
#define HIDD 4608
#define NPARAM 9216            // per-sample conv params (32*32*3*3)
#define KSPLIT 4
#define KCHUNK 1152            // HIDD / KSPLIT

// Scratch (device globals: allocation-free rule)
__device__ float g_ht[HIDD * NB];                 // h transposed [hid][b]
__device__ float g_part[KSPLIT * NB * NPARAM];    // gemm2 k-split partials
__device__ float g_w[NB * NPARAM];                // final per-sample weights

// ---------------------------------------------------------------------------
// packed fp32x2 helpers (FFMA2 path — 2x fp32 MAC throughput on sm_103a)
// ---------------------------------------------------------------------------
typedef unsigned long long u64;

__device__ __forceinline__ u64 pack2(float lo, float hi) {
    u64 r;
    asm("mov.b64 %0, {%1, %2};" : "=l"(r) : "f"(lo), "f"(hi));
    return r;
}
__device__ __forceinline__ u64 splat2(float v) { return pack2(v, v); }

__device__ __forceinline__ u64 fma2(u64 a, u64 b, u64 c) {
    u64 d;
    asm("fma.rn.f32x2 %0, %1, %2, %3;" : "=l"(d) : "l"(a), "l"(b), "l"(c));
    return d;
}
__device__ __forceinline__ float2 unpack2(u64 v) {
    float2 r;
    asm("mov.b64 {%0, %1}, %2;" : "=f"(r.x), "=f"(r.y) : "l"(v));
    return r;
}

// ---------------------------------------------------------------------------
// Kernel 1: h = relu(cond @ W1^T + b1), stored transposed ht[hid][b]
// ---------------------------------------------------------------------------
__global__ void mlp1_kernel(const float* __restrict__ cond,
                            const float* __restrict__ W1,
                            const float* __restrict__ b1) {
    int idx = blockIdx.x * blockDim.x + threadIdx.x;   // 147456 threads
    int hid = idx >> 5;
    int b   = idx & 31;
    const float4* c4 = (const float4*)(cond + b * CONDD);
    const float4* w4 = (const float4*)(W1 + (size_t)hid * CONDD);
    float acc = b1[hid];
#pragma unroll 8
    for (int i = 0; i < CONDD / 4; i++) {
        float4 cv = c4[i];
        float4 wv = w4[i];
        acc += cv.x * wv.x + cv.y * wv.y + cv.z * wv.z + cv.w * wv.w;
    }
    g_ht[hid * 32 + b] = fmaxf(acc, 0.0f);
}

// ---------------------------------------------------------------------------
// Kernel 2: partial[kc][b][p] = sum_{k in chunk kc} ht[k][b] * W2[p][k]
// Tile: 32b x 128p, K-chunk 1152, 256 threads, micro 4b x 4p (f32x2 over p).
// Register double-buffer on global loads.
// ---------------------------------------------------------------------------
__global__ void gemm2_kernel(const float* __restrict__ W2) {
    __shared__ float s_h[32 * 32];       // [kk][b]
    __shared__ float s_w[32 * 132];      // [kk][p] padded row stride 132

    int t     = threadIdx.x;
    int pbase = blockIdx.x * 128;
    int kc    = blockIdx.y;

    int b0 = (t & 7) * 4;
    int p0 = (t >> 3) * 4;

    u64 acc2[4][2];
#pragma unroll
    for (int i = 0; i < 4; i++) { acc2[i][0] = 0; acc2[i][1] = 0; }

    const float4* ht4 = (const float4*)g_ht;
    const float4* W24 = (const float4*)W2;

    // per-thread load indices
    int lh_k  = t >> 3;                 // s_h row
    int lh_c4 = t & 7;                  // s_h float4 col
    int lw_p[4], lw_k4[4];
#pragma unroll
    for (int i = 0; i < 4; i++) {
        int j = t + i * 256;
        lw_p[i]  = j >> 3;
        lw_k4[i] = j & 7;
    }

    // prefetch first tile into registers
    int kbase = kc * KCHUNK;
    float4 rh = ht4[(kbase + lh_k) * 8 + lh_c4];
    float4 rw[4];
#pragma unroll
    for (int i = 0; i < 4; i++)
        rw[i] = W24[(size_t)(pbase + lw_p[i]) * 1152 + (kbase >> 2) + lw_k4[i]];

    for (int ks = 0; ks < KCHUNK; ks += 32) {
        __syncthreads();
        // store prefetched tile to smem
        ((float4*)s_h)[t] = rh;
#pragma unroll
        for (int i = 0; i < 4; i++) {
            int p  = lw_p[i];
            int k4 = lw_k4[i];
            s_w[(k4 * 4 + 0) * 132 + p] = rw[i].x;
            s_w[(k4 * 4 + 1) * 132 + p] = rw[i].y;
            s_w[(k4 * 4 + 2) * 132 + p] = rw[i].z;
            s_w[(k4 * 4 + 3) * 132 + p] = rw[i].w;
        }
        __syncthreads();

        // prefetch next tile (overlaps with compute below)
        if (ks + 32 < KCHUNK) {
            int kn = kc * KCHUNK + ks + 32;
            rh = ht4[(kn + lh_k) * 8 + lh_c4];
#pragma unroll
            for (int i = 0; i < 4; i++)
                rw[i] = W24[(size_t)(pbase + lw_p[i]) * 1152 + (kn >> 2) + lw_k4[i]];
        }

#pragma unroll
        for (int kk = 0; kk < 32; kk++) {
            float4 hv = *(const float4*)&s_h[kk * 32 + b0];
            u64 w01 = *(const u64*)&s_w[kk * 132 + p0];
            u64 w23 = *(const u64*)&s_w[kk * 132 + p0 + 2];
            u64 hs0 = splat2(hv.x), hs1 = splat2(hv.y);
            u64 hs2 = splat2(hv.z), hs3 = splat2(hv.w);
            acc2[0][0] = fma2(hs0, w01, acc2[0][0]);
            acc2[0][1] = fma2(hs0, w23, acc2[0][1]);
            acc2[1][0] = fma2(hs1, w01, acc2[1][0]);
            acc2[1][1] = fma2(hs1, w23, acc2[1][1]);
            acc2[2][0] = fma2(hs2, w01, acc2[2][0]);
            acc2[2][1] = fma2(hs2, w23, acc2[2][1]);
            acc2[3][0] = fma2(hs3, w01, acc2[3][0]);
            acc2[3][1] = fma2(hs3, w23, acc2[3][1]);
        }
    }

    float* dst = g_part + (size_t)kc * (NB * NPARAM);
#pragma unroll
    for (int i = 0; i < 4; i++) {
        float2 lo = unpack2(acc2[i][0]);
        float2 hi = unpack2(acc2[i][1]);
        float4 v  = make_float4(lo.x, lo.y, hi.x, hi.y);
        *(float4*)&dst[(size_t)(b0 + i) * NPARAM + pbase + p0] = v;
    }
}

// ---------------------------------------------------------------------------
// Kernel 3: reduce k-split partials + bias -> g_w[b][p]
// ---------------------------------------------------------------------------
__global__ void reduce_kernel(const float* __restrict__ b2) {
    int idx = blockIdx.x * blockDim.x + threadIdx.x;   // < 294912
    const int n = NB * NPARAM;
    float s = g_part[idx] + g_part[idx + n] + g_part[idx + 2 * n] +
              g_part[idx + 3 * n];
    g_w[idx] = s + b2[idx % NPARAM];
}

// ---------------------------------------------------------------------------
// Kernel 4: per-sample 3x3 conv (pad 1, stride 1), f32x2 packed over y-pair.
// Block: (b, 16y x 64x slab), 512 threads, micro 4co x (2y packed) x 8x.
// Smem: x tile 32ch x 18 x 66 + weights transposed [cin*9+q][co].
// ---------------------------------------------------------------------------
#define SXROWS 18
#define SXROW  66
#define SX_SZ (32 * SXROWS * SXROW)   // 38016 floats
#define SW_SZ (288 * 32)              // 9216 floats

__global__ void __launch_bounds__(512, 1)
conv_kernel(const float* __restrict__ x, float* __restrict__ out) {
    extern __shared__ float smem[];
    float* s_x = smem;               // [cin][row 0..17][col 0..65]
    float* s_w = smem + SX_SZ;       // [cin*9 + ky*3 + kx][co]

    int t   = threadIdx.x;
    int b   = blockIdx.z;
    int gy0 = blockIdx.y * 16;
    int gx0 = blockIdx.x * 64;

    // load per-sample weights, transposing to co-contiguous
    const float* wsrc = g_w + (size_t)b * NPARAM;
    for (int i = t; i < NPARAM; i += 512) {
        int co = i / 288;
        int q  = i - co * 288;       // cin*9 + ky*3 + kx
        s_w[q * 32 + co] = wsrc[i];
    }

    // load x tile with halo (zero pad at image edges)
    for (int i = t; i < SX_SZ; i += 512) {
        int cin = i / (SXROWS * SXROW);
        int rem = i - cin * (SXROWS * SXROW);
        int row = rem / SXROW;
        int col = rem - row * SXROW;
        int gy = gy0 - 1 + row;
        int gx = gx0 - 1 + col;
        float v = 0.0f;
        if (gy >= 0 && gy < HWD && gx >= 0 && gx < HWD)
            v = x[(((size_t)b * 32 + cin) * HWD + gy) * HWD + gx];
        s_x[i] = v;
    }
    __syncthreads();

    int co0 = (t & 7) * 4;
    int g   = t >> 3;          // 0..63
    int y0  = (g >> 3) * 2;    // 0,2,..,14
    int x0  = (g & 7) * 8;     // 0,8,..,56

    // acc2[c][xx] = {out(y0, x0+xx), out(y0+1, x0+xx)} for cout co0+c
    u64 acc2[4][8];
#pragma unroll
    for (int c = 0; c < 4; c++)
#pragma unroll
        for (int xx = 0; xx < 8; xx++) acc2[c][xx] = 0;

    for (int cin = 0; cin < 32; cin++) {
        const float* xb = s_x + cin * (SXROWS * SXROW);
#pragma unroll
        for (int ky = 0; ky < 3; ky++) {
            const float* pr = xb + (y0 + ky) * SXROW + x0;
            // pack activation pairs across the two output rows
            u64 pa[10];
#pragma unroll
            for (int j = 0; j < 10; j++)
                pa[j] = pack2(pr[j], pr[SXROW + j]);

            const float* wq = s_w + (cin * 9 + ky * 3) * 32 + co0;
            float4 w0 = *(const float4*)(wq);
            float4 w1 = *(const float4*)(wq + 32);
            float4 w2 = *(const float4*)(wq + 64);
            float wc0[4] = {w0.x, w0.y, w0.z, w0.w};
            float wc1[4] = {w1.x, w1.y, w1.z, w1.w};
            float wc2[4] = {w2.x, w2.y, w2.z, w2.w};
#pragma unroll
            for (int c = 0; c < 4; c++) {
                u64 wsa = splat2(wc0[c]);
                u64 wsb = splat2(wc1[c]);
                u64 wsc = splat2(wc2[c]);
#pragma unroll
                for (int xx = 0; xx < 8; xx++) {
                    acc2[c][xx] = fma2(wsa, pa[xx],     acc2[c][xx]);
                    acc2[c][xx] = fma2(wsb, pa[xx + 1], acc2[c][xx]);
                    acc2[c][xx] = fma2(wsc, pa[xx + 2], acc2[c][xx]);
                }
            }
        }
    }

    // epilogue: unpack y-pairs, write two rows per cout
#pragma unroll
    for (int c = 0; c < 4; c++) {
        float2 v[8];
#pragma unroll
        for (int xx = 0; xx < 8; xx++) v[xx] = unpack2(acc2[c][xx]);
        float* po = out +
            ((size_t)(b * 32 + co0 + c) * HWD + (gy0 + y0)) * HWD + gx0 + x0;
        *(float4*)(po)           = make_float4(v[0].x, v[1].x, v[2].x, v[3].x);
        *(float4*)(po + 4)       = make_float4(v[4].x, v[5].x, v[6].x, v[7].x);
        *(float4*)(po + HWD)     = make_float4(v[0].y, v[1].y, v[2].y, v[3].y);
        *(float4*)(po + HWD + 4) = make_float4(v[4].y, v[5].y, v[6].y, v[7].y);
    }
}

// ---------------------------------------------------------------------------
extern "C" void kernel_launch(void* const* d_in, const int* in_sizes, int n_in,
                              void* d_out, int out_size) {
    const float* x    = (const float*)d_in[0];
    const float* cond = (const float*)d_in[1];
    const float* W1   = (const float*)d_in[2];
    const float* b1   = (const float*)d_in[3];
    const float* W2   = (const float*)d_in[4];
    const float* b2   = (const float*)d_in[5];
    float* out = (float*)d_out;

    const int conv_smem = (SX_SZ + SW_SZ) * sizeof(float);   // 188928 B
    cudaFuncSetAttribute(conv_kernel,
                         cudaFuncAttributeMaxDynamicSharedMemorySize,
                         conv_smem);

    mlp1_kernel<<<(HIDD * NB) / 256, 256>>>(cond, W1, b1);
    gemm2_kernel<<<dim3(NPARAM / 128, KSPLIT), 256>>>(W2);
    reduce_kernel<<<(NB * NPARAM) / 256, 256>>>(b2);
    conv_kernel<<<dim3(HWD / 64, HWD / 16, NB), 512, conv_smem>>>(x, out);
}